// round 15
// baseline (speedup 1.0000x reference)
#include <cuda_runtime.h>
#include <cuda_bf16.h>

// Problem constants
#define NC 4
#define NN 512
#define ED 512
#define PD 64
#define NH 32
#define HD 16

// wbs row stride: 40 -> B-fragment bank conflict-free (bias kernel)
#define WS 40

// f32x2 packed-math helpers (sm_100+)
#define FMA2(acc, a, b) asm("fma.rn.f32x2 %0, %1, %2, %0;" : "+l"(acc) : "l"(a), "l"(b))
#define MUL2(d, a, b)   asm("mul.rn.f32x2 %0, %1, %2;" : "=l"(d) : "l"(a), "l"(b))
#define PACK2(d, x)     asm("mov.b64 %0, {%1, %1};" : "=l"(d) : "f"(x))
#define UNPACK2(lo, hi, v) asm("mov.b64 {%0, %1}, %2;" : "=f"(lo), "=f"(hi) : "l"(v))

#define CVT_TF32(u, f) asm("cvt.rna.tf32.f32 %0, %1;" : "=r"(u) : "f"(f))

__device__ __forceinline__ void mma_tf32(float& d0, float& d1, float& d2, float& d3,
                                         unsigned a0, unsigned a1, unsigned a2, unsigned a3,
                                         unsigned b0, unsigned b1) {
    asm volatile("mma.sync.aligned.m16n8k8.row.col.f32.tf32.tf32.f32 "
                 "{%0,%1,%2,%3}, {%4,%5,%6,%7}, {%8,%9}, {%0,%1,%2,%3};"
                 : "+f"(d0), "+f"(d1), "+f"(d2), "+f"(d3)
                 : "r"(a0), "r"(a1), "r"(a2), "r"(a3), "r"(b0), "r"(b1));
}

// Scratch (static device arrays; no allocations allowed)
__device__ float g_xq[NC * NN * ED];
__device__ float g_q [NC * NN * ED];
__device__ float g_k [NC * NN * ED];
__device__ float g_v [NC * NN * ED];
__device__ float g_vf[NC * NN * NH];                 // [c, j, h]
__device__ float g_bias[(size_t)NC * NN * NN * NH];  // [c, i, j, h]

// ---------------------------------------------------------------------------
// Kernel A: LayerNorm(query) -> g_xq.
// ---------------------------------------------------------------------------
__global__ void ln_q_kernel(const float* __restrict__ x,
                            const float* __restrict__ g,
                            const float* __restrict__ b) {
    int row = blockIdx.x;
    const float* xr = x + (size_t)row * ED;
    float* o = g_xq + (size_t)row * ED;
    int tid = threadIdx.x;  // 128
    float v[4];
    float s = 0.f, s2 = 0.f;
#pragma unroll
    for (int t = 0; t < 4; t++) {
        float vv = xr[tid + t * 128];
        v[t] = vv; s += vv; s2 += vv * vv;
    }
#pragma unroll
    for (int off = 16; off; off >>= 1) {
        s  += __shfl_down_sync(0xffffffffu, s,  off);
        s2 += __shfl_down_sync(0xffffffffu, s2, off);
    }
    __shared__ float sh[8];
    if ((tid & 31) == 0) { sh[tid >> 5] = s; sh[4 + (tid >> 5)] = s2; }
    __syncthreads();
    float S  = sh[0] + sh[1] + sh[2] + sh[3];
    float S2 = sh[4] + sh[5] + sh[6] + sh[7];
    float mu   = S * (1.f / ED);
    float var  = S2 * (1.f / ED) - mu * mu;
    float rstd = rsqrtf(var + 1e-5f);
#pragma unroll
    for (int t = 0; t < 4; t++) {
        int e = tid + t * 128;
        o[e] = (v[t] - mu) * rstd * g[e] + b[e];
    }
}

// ---------------------------------------------------------------------------
// Kernel B: QKV projection GEMM on tensor cores (R14-proven, 3-mma tf32).
// ---------------------------------------------------------------------------
#define QBK 16
__global__ void __launch_bounds__(256) qkv_gemm_tc(
    const float* __restrict__ Wq, const float* __restrict__ Wk,
    const float* __restrict__ Wv) {
    const float* W; float* O; float scale = 1.f;
    if (blockIdx.z == 0)      { W = Wq; O = g_q; scale = 0.25f; }
    else if (blockIdx.z == 1) { W = Wk; O = g_k; }
    else                      { W = Wv; O = g_v; }
    const float* A = g_xq;

    __shared__ float Ahi[128 * 20], Alo[128 * 20];
    __shared__ float Bhi[64 * 20],  Blo[64 * 20];

    int tid = threadIdx.x;
    int m0 = blockIdx.y * 128, n0 = blockIdx.x * 64;
    int w = tid >> 5, lane = tid & 31;
    int lr = lane >> 2, lc = lane & 3;
    int arow0 = w * 16 + lr;

    float d[8][4];
#pragma unroll
    for (int nc = 0; nc < 8; nc++)
        d[nc][0] = d[nc][1] = d[nc][2] = d[nc][3] = 0.f;

    for (int k0 = 0; k0 < ED; k0 += QBK) {
        __syncthreads();
#pragma unroll
        for (int t = 0; t < 2; t++) {
            int idx = tid + t * 256;
            int row = idx >> 2, f4 = idx & 3;
            float4 v = *(const float4*)&A[(size_t)(m0 + row) * ED + k0 + f4 * 4];
            float4 hi4, lo4;
            unsigned u;
            CVT_TF32(u, v.x); hi4.x = __uint_as_float(u); { float r = v.x - hi4.x; CVT_TF32(u, r); lo4.x = __uint_as_float(u); }
            CVT_TF32(u, v.y); hi4.y = __uint_as_float(u); { float r = v.y - hi4.y; CVT_TF32(u, r); lo4.y = __uint_as_float(u); }
            CVT_TF32(u, v.z); hi4.z = __uint_as_float(u); { float r = v.z - hi4.z; CVT_TF32(u, r); lo4.z = __uint_as_float(u); }
            CVT_TF32(u, v.w); hi4.w = __uint_as_float(u); { float r = v.w - hi4.w; CVT_TF32(u, r); lo4.w = __uint_as_float(u); }
            *(float4*)&Ahi[row * 20 + f4 * 4] = hi4;
            *(float4*)&Alo[row * 20 + f4 * 4] = lo4;
        }
        {
            int row = tid >> 2, f4 = tid & 3;
            float4 v = *(const float4*)&W[(size_t)(n0 + row) * ED + k0 + f4 * 4];
            float4 hi4, lo4;
            unsigned u;
            CVT_TF32(u, v.x); hi4.x = __uint_as_float(u); { float r = v.x - hi4.x; CVT_TF32(u, r); lo4.x = __uint_as_float(u); }
            CVT_TF32(u, v.y); hi4.y = __uint_as_float(u); { float r = v.y - hi4.y; CVT_TF32(u, r); lo4.y = __uint_as_float(u); }
            CVT_TF32(u, v.z); hi4.z = __uint_as_float(u); { float r = v.z - hi4.z; CVT_TF32(u, r); lo4.z = __uint_as_float(u); }
            CVT_TF32(u, v.w); hi4.w = __uint_as_float(u); { float r = v.w - hi4.w; CVT_TF32(u, r); lo4.w = __uint_as_float(u); }
            *(float4*)&Bhi[row * 20 + f4 * 4] = hi4;
            *(float4*)&Blo[row * 20 + f4 * 4] = lo4;
        }
        __syncthreads();

#pragma unroll
        for (int kc = 0; kc < QBK / 8; kc++) {
            unsigned ah[4], al[4];
            ah[0] = __float_as_uint(Ahi[arow0 * 20 + kc * 8 + lc]);
            ah[1] = __float_as_uint(Ahi[(arow0 + 8) * 20 + kc * 8 + lc]);
            ah[2] = __float_as_uint(Ahi[arow0 * 20 + kc * 8 + lc + 4]);
            ah[3] = __float_as_uint(Ahi[(arow0 + 8) * 20 + kc * 8 + lc + 4]);
            al[0] = __float_as_uint(Alo[arow0 * 20 + kc * 8 + lc]);
            al[1] = __float_as_uint(Alo[(arow0 + 8) * 20 + kc * 8 + lc]);
            al[2] = __float_as_uint(Alo[arow0 * 20 + kc * 8 + lc + 4]);
            al[3] = __float_as_uint(Alo[(arow0 + 8) * 20 + kc * 8 + lc + 4]);
#pragma unroll
            for (int nc = 0; nc < 8; nc++) {
                int nrow = nc * 8 + lr;
                unsigned bh0 = __float_as_uint(Bhi[nrow * 20 + kc * 8 + lc]);
                unsigned bh1 = __float_as_uint(Bhi[nrow * 20 + kc * 8 + lc + 4]);
                unsigned bl0 = __float_as_uint(Blo[nrow * 20 + kc * 8 + lc]);
                unsigned bl1 = __float_as_uint(Blo[nrow * 20 + kc * 8 + lc + 4]);
                mma_tf32(d[nc][0], d[nc][1], d[nc][2], d[nc][3],
                         ah[0], ah[1], ah[2], ah[3], bh0, bh1);
                mma_tf32(d[nc][0], d[nc][1], d[nc][2], d[nc][3],
                         ah[0], ah[1], ah[2], ah[3], bl0, bl1);
                mma_tf32(d[nc][0], d[nc][1], d[nc][2], d[nc][3],
                         al[0], al[1], al[2], al[3], bh0, bh1);
            }
        }
    }

    size_t row = (size_t)(m0 + arow0);
#pragma unroll
    for (int nc = 0; nc < 8; nc++) {
        int col = n0 + nc * 8 + 2 * lc;
        *(float2*)&O[row * ED + col] =
            make_float2(d[nc][0] * scale, d[nc][1] * scale);
        *(float2*)&O[(row + 8) * ED + col] =
            make_float2(d[nc][2] * scale, d[nc][3] * scale);
    }
}

// ---------------------------------------------------------------------------
// Kernel C: vf[c,j,h] = sum_d v[c,j,h*16+d] * Wf[h*16+d]
// ---------------------------------------------------------------------------
__global__ void vf_kernel(const float* __restrict__ Wf) {
    int idx = blockIdx.x * blockDim.x + threadIdx.x;
    int h = idx & 31;
    int cj = idx >> 5;
    const float* vr = g_v + (size_t)cj * ED + h * HD;
    const float* wf = Wf + h * HD;
    float s = 0.f;
#pragma unroll
    for (int d = 0; d < HD; d++) s += vr[d] * wf[d];
    g_vf[(size_t)cj * NH + h] = s;
}

// ---------------------------------------------------------------------------
// Kernel E: bias GEMM on tensor cores, LN folded into epilogue (R12 exact).
// ---------------------------------------------------------------------------
#define BM 128
__global__ void __launch_bounds__(256) bias_kernel(
    const float* __restrict__ pair, const float* __restrict__ lnpg,
    const float* __restrict__ lnpb, const float* __restrict__ Wb,
    const float* __restrict__ bb) {
    __shared__ float pt[BM * 68];
    __shared__ float wbs[64 * WS];
    __shared__ float mus[BM], rstds[BM];
    __shared__ float ssm[NH], c1sm[NH];
    int tid = threadIdx.x;
    size_t rowbase = (size_t)blockIdx.x * BM;

    const float4* src = (const float4*)(pair + rowbase * PD);
#pragma unroll
    for (int t = 0; t < 8; t++) {
        int idx = tid + t * 256;
        int row = idx >> 4, f4 = idx & 15;
        float4 v = src[idx];
        *(float4*)&pt[row * 68 + f4 * 4] = v;
    }
    for (int idx = tid; idx < 2048; idx += 256) {
        int n = idx >> 6, k = idx & 63;
        wbs[k * WS + n] = lnpg[k] * Wb[idx];
    }
    __syncthreads();

    {
        int row = tid >> 1, half = tid & 1;
        const float* pr = pt + row * 68 + half * 32;
        float s = 0.f, s2 = 0.f;
#pragma unroll
        for (int t = 0; t < 8; t++) {
            float4 v = *(const float4*)&pr[t * 4];
            s  += v.x + v.y + v.z + v.w;
            s2 += v.x * v.x + v.y * v.y + v.z * v.z + v.w * v.w;
        }
        s  += __shfl_xor_sync(0xffffffffu, s, 1);
        s2 += __shfl_xor_sync(0xffffffffu, s2, 1);
        if (half == 0) {
            float mu  = s * (1.f / PD);
            float var = s2 * (1.f / PD) - mu * mu;
            mus[row]   = mu;
            rstds[row] = rsqrtf(var + 1e-5f);
        }
    }
    {
        int h = tid >> 3, kq = tid & 7;
        float sv = 0.f, c1 = 0.f;
#pragma unroll
        for (int t = 0; t < 8; t++) {
            int k = kq * 8 + t;
            sv += wbs[k * WS + h];
            c1 += lnpb[k] * Wb[h * PD + k];
        }
#pragma unroll
        for (int off = 1; off < 8; off <<= 1) {
            sv += __shfl_xor_sync(0xffffffffu, sv, off, 8);
            c1 += __shfl_xor_sync(0xffffffffu, c1, off, 8);
        }
        if (kq == 0) { ssm[h] = sv; c1sm[h] = c1 + bb[h]; }
    }
    __syncthreads();

    int w = tid >> 5, lane = tid & 31;
    int lr = lane >> 2, lc = lane & 3;
    int arow0 = w * 16 + lr;

    float d[4][4];
#pragma unroll
    for (int nc = 0; nc < 4; nc++)
        d[nc][0] = d[nc][1] = d[nc][2] = d[nc][3] = 0.f;

#pragma unroll
    for (int kc = 0; kc < 8; kc++) {
        float af[4];
        af[0] = pt[arow0 * 68 + kc * 8 + lc];
        af[1] = pt[(arow0 + 8) * 68 + kc * 8 + lc];
        af[2] = pt[arow0 * 68 + kc * 8 + lc + 4];
        af[3] = pt[(arow0 + 8) * 68 + kc * 8 + lc + 4];
        unsigned ah[4], al[4];
#pragma unroll
        for (int t = 0; t < 4; t++) {
            CVT_TF32(ah[t], af[t]);
            float res = af[t] - __uint_as_float(ah[t]);
            CVT_TF32(al[t], res);
        }
#pragma unroll
        for (int nc = 0; nc < 4; nc++) {
            float bf0 = wbs[(kc * 8 + lc) * WS + nc * 8 + lr];
            float bf1 = wbs[(kc * 8 + lc + 4) * WS + nc * 8 + lr];
            unsigned bh0, bh1, bl0, bl1;
            CVT_TF32(bh0, bf0);
            CVT_TF32(bh1, bf1);
            float r0 = bf0 - __uint_as_float(bh0);
            float r1 = bf1 - __uint_as_float(bh1);
            CVT_TF32(bl0, r0);
            CVT_TF32(bl1, r1);
            mma_tf32(d[nc][0], d[nc][1], d[nc][2], d[nc][3],
                     ah[0], ah[1], ah[2], ah[3], bh0, bh1);
            mma_tf32(d[nc][0], d[nc][1], d[nc][2], d[nc][3],
                     ah[0], ah[1], ah[2], ah[3], bl0, bl1);
            mma_tf32(d[nc][0], d[nc][1], d[nc][2], d[nc][3],
                     al[0], al[1], al[2], al[3], bh0, bh1);
        }
    }

    float mu0 = mus[arow0],     rs0 = rstds[arow0];
    float mu1 = mus[arow0 + 8], rs1 = rstds[arow0 + 8];
    size_t row = rowbase + arow0;
#pragma unroll
    for (int nc = 0; nc < 4; nc++) {
        int col = nc * 8 + 2 * lc;
        float s0 = ssm[col], s1 = ssm[col + 1];
        float c0 = c1sm[col], c1v = c1sm[col + 1];
        float2 o0, o1;
        o0.x = rs0 * (d[nc][0] - mu0 * s0) + c0;
        o0.y = rs0 * (d[nc][1] - mu0 * s1) + c1v;
        o1.x = rs1 * (d[nc][2] - mu1 * s0) + c0;
        o1.y = rs1 * (d[nc][3] - mu1 * s1) + c1v;
        *(float2*)&g_bias[row * NH + col]       = o0;
        *(float2*)&g_bias[(row + 8) * NH + col] = o1;
    }
}

// ---------------------------------------------------------------------------
// Kernel F: streaming attention + force.  1024 threads = 32 warps.
// Warp w: SINGLE i-row ii = w>>3, j-slot = w&7 (j == slot mod 8).
// q is only 16 regs/warp -> ~64 regs total -> 32 warps/SM resident.
// K rows hit L1 (4 warps per j-slot read the same rows near-simultaneously).
// ---------------------------------------------------------------------------
__global__ void __launch_bounds__(1024, 1) attn_kernel(
    const float* __restrict__ delta, float* __restrict__ out) {
    int c = blockIdx.y;
    int ibase = blockIdx.x * 4;
    int tid = threadIdx.x;
    int w = tid >> 5, h = tid & 31;
    int ii = w >> 3, jslot = w & 7;

    const size_t cb = (size_t)(c * NN) + ibase;
    const size_t crow = cb + ii;

    const float* qp = g_q + crow * ED + h * HD;
    ulonglong2 q0 = *(const ulonglong2*)(qp + 0);
    ulonglong2 q1 = *(const ulonglong2*)(qp + 4);
    ulonglong2 q2 = *(const ulonglong2*)(qp + 8);
    ulonglong2 q3 = *(const ulonglong2*)(qp + 12);

    float l = 0.f, n0 = 0.f, n1 = 0.f, n2 = 0.f;

#pragma unroll 2
    for (int j = jslot; j < NN; j += 8) {
        const float* kp = g_k + ((size_t)(c * NN) + j) * ED + h * HD;
        ulonglong2 k0 = *(const ulonglong2*)(kp + 0);
        ulonglong2 k1 = *(const ulonglong2*)(kp + 4);
        ulonglong2 k2 = *(const ulonglong2*)(kp + 8);
        ulonglong2 k3 = *(const ulonglong2*)(kp + 12);
        float vfv = g_vf[((size_t)(c * NN) + j) * NH + h];
        const float* dp = delta + (crow * NN + j) * 3;
        float bias = g_bias[(crow * NN + j) * NH + h];

        unsigned long long a;
        MUL2(a, q0.x, k0.x);
        FMA2(a, q0.y, k0.y);
        FMA2(a, q1.x, k1.x);
        FMA2(a, q1.y, k1.y);
        FMA2(a, q2.x, k2.x);
        FMA2(a, q2.y, k2.y);
        FMA2(a, q3.x, k3.x);
        FMA2(a, q3.y, k3.y);
        float lo, hi; UNPACK2(lo, hi, a);
        float z = lo + hi + bias;
        float we = __expf(z);
        float wv = we * vfv;
        float d0 = dp[0];
        float d1 = dp[1];
        float d2 = dp[2];
        l  += we;
        n0 += wv * d0;
        n1 += wv * d1;
        n2 += wv * d2;
    }

    __shared__ float ms[32][32][4];
    *(float4*)&ms[w][h][0] = make_float4(l, n0, n1, n2);
    __syncthreads();

    if (w < 4) {
        int i2 = w;
        float L = 0.f, F0 = 0.f, F1 = 0.f, F2 = 0.f;
#pragma unroll
        for (int k = 0; k < 8; k++) {
            float4 a = *(const float4*)&ms[i2 * 8 + k][h][0];
            L += a.x; F0 += a.y; F1 += a.z; F2 += a.w;
        }
        // per-(i, head) normalization BEFORE summing over heads
        float inv = 1.f / L;
        F0 *= inv; F1 *= inv; F2 *= inv;
#pragma unroll
        for (int off = 16; off; off >>= 1) {
            F0 += __shfl_down_sync(0xffffffffu, F0, off);
            F1 += __shfl_down_sync(0xffffffffu, F1, off);
            F2 += __shfl_down_sync(0xffffffffu, F2, off);
        }
        if (h == 0) {
            float* op = out + (cb + i2) * 3;
            op[0] = F0; op[1] = F1; op[2] = F2;
        }
    }
}

// ---------------------------------------------------------------------------
// Host launch
// ---------------------------------------------------------------------------
extern "C" void kernel_launch(void* const* d_in, const int* in_sizes, int n_in,
                              void* d_out, int out_size) {
    const float* query = (const float*)d_in[0];
    const float* pair  = (const float*)d_in[1];
    const float* delta = (const float*)d_in[2];
    const float* lnqg  = (const float*)d_in[3];
    const float* lnqb  = (const float*)d_in[4];
    const float* lnpg  = (const float*)d_in[5];
    const float* lnpb  = (const float*)d_in[6];
    const float* Wq    = (const float*)d_in[7];
    const float* Wk    = (const float*)d_in[8];
    const float* Wv    = (const float*)d_in[9];
    const float* Wb    = (const float*)d_in[10];
    const float* bb    = (const float*)d_in[11];
    const float* Wf    = (const float*)d_in[12];
    float* out = (float*)d_out;

    ln_q_kernel<<<NC * NN, 128>>>(query, lnqg, lnqb);

    dim3 gg(ED / 64, (NC * NN) / 128, 3);
    qkv_gemm_tc<<<gg, 256>>>(Wq, Wk, Wv);

    vf_kernel<<<(NC * NN * NH) / 256, 256>>>(Wf);

    bias_kernel<<<(NC * NN * NN) / BM, 256>>>(pair, lnpg, lnpb, Wb, bb);

    attn_kernel<<<dim3(NN / 4, NC), 1024>>>(delta, out);
}

// round 16
// speedup vs baseline: 1.4878x; 1.4878x over previous
#include <cuda_runtime.h>
#include <cuda_bf16.h>

// Problem constants
#define NC 4
#define NN 512
#define ED 512
#define PD 64
#define NH 32
#define HD 16

// wbs row stride: 40 -> B-fragment bank conflict-free (bias kernel)
#define WS 40

// f32x2 packed-math helpers (sm_100+)
#define FMA2(acc, a, b) asm("fma.rn.f32x2 %0, %1, %2, %0;" : "+l"(acc) : "l"(a), "l"(b))
#define MUL2(d, a, b)   asm("mul.rn.f32x2 %0, %1, %2;" : "=l"(d) : "l"(a), "l"(b))
#define PACK2(d, x)     asm("mov.b64 %0, {%1, %1};" : "=l"(d) : "f"(x))
#define UNPACK2(lo, hi, v) asm("mov.b64 {%0, %1}, %2;" : "=f"(lo), "=f"(hi) : "l"(v))

#define CVT_TF32(u, f) asm("cvt.rna.tf32.f32 %0, %1;" : "=r"(u) : "f"(f))

__device__ __forceinline__ void mma_tf32(float& d0, float& d1, float& d2, float& d3,
                                         unsigned a0, unsigned a1, unsigned a2, unsigned a3,
                                         unsigned b0, unsigned b1) {
    asm volatile("mma.sync.aligned.m16n8k8.row.col.f32.tf32.tf32.f32 "
                 "{%0,%1,%2,%3}, {%4,%5,%6,%7}, {%8,%9}, {%0,%1,%2,%3};"
                 : "+f"(d0), "+f"(d1), "+f"(d2), "+f"(d3)
                 : "r"(a0), "r"(a1), "r"(a2), "r"(a3), "r"(b0), "r"(b1));
}

// Scratch (static device arrays; no allocations allowed)
__device__ float g_xq[NC * NN * ED];
__device__ float g_q [NC * NN * ED];
__device__ float g_k [NC * NN * ED];
__device__ float g_v [NC * NN * ED];
__device__ float g_vf[NC * NN * NH];                 // [c, j, h]
__device__ float g_bias[(size_t)NC * NN * NN * NH];  // [c, i, j, h]

// ---------------------------------------------------------------------------
// Kernel A: LayerNorm(query) -> g_xq.
// ---------------------------------------------------------------------------
__global__ void ln_q_kernel(const float* __restrict__ x,
                            const float* __restrict__ g,
                            const float* __restrict__ b) {
    int row = blockIdx.x;
    const float* xr = x + (size_t)row * ED;
    float* o = g_xq + (size_t)row * ED;
    int tid = threadIdx.x;  // 128
    float v[4];
    float s = 0.f, s2 = 0.f;
#pragma unroll
    for (int t = 0; t < 4; t++) {
        float vv = xr[tid + t * 128];
        v[t] = vv; s += vv; s2 += vv * vv;
    }
#pragma unroll
    for (int off = 16; off; off >>= 1) {
        s  += __shfl_down_sync(0xffffffffu, s,  off);
        s2 += __shfl_down_sync(0xffffffffu, s2, off);
    }
    __shared__ float sh[8];
    if ((tid & 31) == 0) { sh[tid >> 5] = s; sh[4 + (tid >> 5)] = s2; }
    __syncthreads();
    float S  = sh[0] + sh[1] + sh[2] + sh[3];
    float S2 = sh[4] + sh[5] + sh[6] + sh[7];
    float mu   = S * (1.f / ED);
    float var  = S2 * (1.f / ED) - mu * mu;
    float rstd = rsqrtf(var + 1e-5f);
#pragma unroll
    for (int t = 0; t < 4; t++) {
        int e = tid + t * 128;
        o[e] = (v[t] - mu) * rstd * g[e] + b[e];
    }
}

// ---------------------------------------------------------------------------
// Kernel B: QKV projection GEMM on tensor cores (R14-proven, 3-mma tf32).
// V case (blockIdx.z==2) additionally computes vf[m][h] = sum_d v*Wf in the
// epilogue (the block's 64 columns = 4 complete heads), replacing vf_kernel.
// ---------------------------------------------------------------------------
#define QBK 16
__global__ void __launch_bounds__(256) qkv_gemm_tc(
    const float* __restrict__ Wq, const float* __restrict__ Wk,
    const float* __restrict__ Wv, const float* __restrict__ Wf) {
    const float* W; float* O; float scale = 1.f;
    if (blockIdx.z == 0)      { W = Wq; O = g_q; scale = 0.25f; }
    else if (blockIdx.z == 1) { W = Wk; O = g_k; }
    else                      { W = Wv; O = g_v; }
    const float* A = g_xq;

    __shared__ float Ahi[128 * 20], Alo[128 * 20];
    __shared__ float Bhi[64 * 20],  Blo[64 * 20];
    __shared__ float vft[128][4];   // per-block vf tile (V case only)

    int tid = threadIdx.x;
    int m0 = blockIdx.y * 128, n0 = blockIdx.x * 64;
    int w = tid >> 5, lane = tid & 31;
    int lr = lane >> 2, lc = lane & 3;
    int arow0 = w * 16 + lr;

    if (blockIdx.z == 2) {
        for (int idx = tid; idx < 128 * 4; idx += 256)
            ((float*)vft)[idx] = 0.f;
    }

    float d[8][4];
#pragma unroll
    for (int nc = 0; nc < 8; nc++)
        d[nc][0] = d[nc][1] = d[nc][2] = d[nc][3] = 0.f;

    for (int k0 = 0; k0 < ED; k0 += QBK) {
        __syncthreads();
#pragma unroll
        for (int t = 0; t < 2; t++) {
            int idx = tid + t * 256;
            int row = idx >> 2, f4 = idx & 3;
            float4 v = *(const float4*)&A[(size_t)(m0 + row) * ED + k0 + f4 * 4];
            float4 hi4, lo4;
            unsigned u;
            CVT_TF32(u, v.x); hi4.x = __uint_as_float(u); { float r = v.x - hi4.x; CVT_TF32(u, r); lo4.x = __uint_as_float(u); }
            CVT_TF32(u, v.y); hi4.y = __uint_as_float(u); { float r = v.y - hi4.y; CVT_TF32(u, r); lo4.y = __uint_as_float(u); }
            CVT_TF32(u, v.z); hi4.z = __uint_as_float(u); { float r = v.z - hi4.z; CVT_TF32(u, r); lo4.z = __uint_as_float(u); }
            CVT_TF32(u, v.w); hi4.w = __uint_as_float(u); { float r = v.w - hi4.w; CVT_TF32(u, r); lo4.w = __uint_as_float(u); }
            *(float4*)&Ahi[row * 20 + f4 * 4] = hi4;
            *(float4*)&Alo[row * 20 + f4 * 4] = lo4;
        }
        {
            int row = tid >> 2, f4 = tid & 3;
            float4 v = *(const float4*)&W[(size_t)(n0 + row) * ED + k0 + f4 * 4];
            float4 hi4, lo4;
            unsigned u;
            CVT_TF32(u, v.x); hi4.x = __uint_as_float(u); { float r = v.x - hi4.x; CVT_TF32(u, r); lo4.x = __uint_as_float(u); }
            CVT_TF32(u, v.y); hi4.y = __uint_as_float(u); { float r = v.y - hi4.y; CVT_TF32(u, r); lo4.y = __uint_as_float(u); }
            CVT_TF32(u, v.z); hi4.z = __uint_as_float(u); { float r = v.z - hi4.z; CVT_TF32(u, r); lo4.z = __uint_as_float(u); }
            CVT_TF32(u, v.w); hi4.w = __uint_as_float(u); { float r = v.w - hi4.w; CVT_TF32(u, r); lo4.w = __uint_as_float(u); }
            *(float4*)&Bhi[row * 20 + f4 * 4] = hi4;
            *(float4*)&Blo[row * 20 + f4 * 4] = lo4;
        }
        __syncthreads();

#pragma unroll
        for (int kc = 0; kc < QBK / 8; kc++) {
            unsigned ah[4], al[4];
            ah[0] = __float_as_uint(Ahi[arow0 * 20 + kc * 8 + lc]);
            ah[1] = __float_as_uint(Ahi[(arow0 + 8) * 20 + kc * 8 + lc]);
            ah[2] = __float_as_uint(Ahi[arow0 * 20 + kc * 8 + lc + 4]);
            ah[3] = __float_as_uint(Ahi[(arow0 + 8) * 20 + kc * 8 + lc + 4]);
            al[0] = __float_as_uint(Alo[arow0 * 20 + kc * 8 + lc]);
            al[1] = __float_as_uint(Alo[(arow0 + 8) * 20 + kc * 8 + lc]);
            al[2] = __float_as_uint(Alo[arow0 * 20 + kc * 8 + lc + 4]);
            al[3] = __float_as_uint(Alo[(arow0 + 8) * 20 + kc * 8 + lc + 4]);
#pragma unroll
            for (int nc = 0; nc < 8; nc++) {
                int nrow = nc * 8 + lr;
                unsigned bh0 = __float_as_uint(Bhi[nrow * 20 + kc * 8 + lc]);
                unsigned bh1 = __float_as_uint(Bhi[nrow * 20 + kc * 8 + lc + 4]);
                unsigned bl0 = __float_as_uint(Blo[nrow * 20 + kc * 8 + lc]);
                unsigned bl1 = __float_as_uint(Blo[nrow * 20 + kc * 8 + lc + 4]);
                mma_tf32(d[nc][0], d[nc][1], d[nc][2], d[nc][3],
                         ah[0], ah[1], ah[2], ah[3], bh0, bh1);
                mma_tf32(d[nc][0], d[nc][1], d[nc][2], d[nc][3],
                         ah[0], ah[1], ah[2], ah[3], bl0, bl1);
                mma_tf32(d[nc][0], d[nc][1], d[nc][2], d[nc][3],
                         al[0], al[1], al[2], al[3], bh0, bh1);
            }
        }
    }

    size_t row = (size_t)(m0 + arow0);
#pragma unroll
    for (int nc = 0; nc < 8; nc++) {
        int col = n0 + nc * 8 + 2 * lc;
        *(float2*)&O[row * ED + col] =
            make_float2(d[nc][0] * scale, d[nc][1] * scale);
        *(float2*)&O[(row + 8) * ED + col] =
            make_float2(d[nc][2] * scale, d[nc][3] * scale);
    }

    // ---- fused vf for the V case: this block's 64 cols = 4 complete heads ----
    if (blockIdx.z == 2) {
        __syncthreads();   // vft zero-init complete (and O writes irrelevant)
#pragma unroll
        for (int nc = 0; nc < 8; nc++) {
            int cl = nc * 8 + 2 * lc;           // local col 0..63
            int hl = nc >> 1;                    // local head 0..3
            float w0 = Wf[n0 + cl];
            float w1 = Wf[n0 + cl + 1];
            atomicAdd(&vft[arow0][hl],     d[nc][0] * w0 + d[nc][1] * w1);
            atomicAdd(&vft[arow0 + 8][hl], d[nc][2] * w0 + d[nc][3] * w1);
        }
        __syncthreads();
        int h0 = n0 >> 4;   // first head of this block
        for (int idx = tid; idx < 128 * 4; idx += 256) {
            int r = idx >> 2, hl = idx & 3;
            g_vf[(size_t)(m0 + r) * NH + h0 + hl] = vft[r][hl];
        }
    }
}

// ---------------------------------------------------------------------------
// Kernel E: bias GEMM on tensor cores, LN folded into epilogue (R12 exact).
// ---------------------------------------------------------------------------
#define BM 128
__global__ void __launch_bounds__(256) bias_kernel(
    const float* __restrict__ pair, const float* __restrict__ lnpg,
    const float* __restrict__ lnpb, const float* __restrict__ Wb,
    const float* __restrict__ bb) {
    __shared__ float pt[BM * 68];
    __shared__ float wbs[64 * WS];
    __shared__ float mus[BM], rstds[BM];
    __shared__ float ssm[NH], c1sm[NH];
    int tid = threadIdx.x;
    size_t rowbase = (size_t)blockIdx.x * BM;

    const float4* src = (const float4*)(pair + rowbase * PD);
#pragma unroll
    for (int t = 0; t < 8; t++) {
        int idx = tid + t * 256;
        int row = idx >> 4, f4 = idx & 15;
        float4 v = src[idx];
        *(float4*)&pt[row * 68 + f4 * 4] = v;
    }
    for (int idx = tid; idx < 2048; idx += 256) {
        int n = idx >> 6, k = idx & 63;
        wbs[k * WS + n] = lnpg[k] * Wb[idx];
    }
    __syncthreads();

    {
        int row = tid >> 1, half = tid & 1;
        const float* pr = pt + row * 68 + half * 32;
        float s = 0.f, s2 = 0.f;
#pragma unroll
        for (int t = 0; t < 8; t++) {
            float4 v = *(const float4*)&pr[t * 4];
            s  += v.x + v.y + v.z + v.w;
            s2 += v.x * v.x + v.y * v.y + v.z * v.z + v.w * v.w;
        }
        s  += __shfl_xor_sync(0xffffffffu, s, 1);
        s2 += __shfl_xor_sync(0xffffffffu, s2, 1);
        if (half == 0) {
            float mu  = s * (1.f / PD);
            float var = s2 * (1.f / PD) - mu * mu;
            mus[row]   = mu;
            rstds[row] = rsqrtf(var + 1e-5f);
        }
    }
    {
        int h = tid >> 3, kq = tid & 7;
        float sv = 0.f, c1 = 0.f;
#pragma unroll
        for (int t = 0; t < 8; t++) {
            int k = kq * 8 + t;
            sv += wbs[k * WS + h];
            c1 += lnpb[k] * Wb[h * PD + k];
        }
#pragma unroll
        for (int off = 1; off < 8; off <<= 1) {
            sv += __shfl_xor_sync(0xffffffffu, sv, off, 8);
            c1 += __shfl_xor_sync(0xffffffffu, c1, off, 8);
        }
        if (kq == 0) { ssm[h] = sv; c1sm[h] = c1 + bb[h]; }
    }
    __syncthreads();

    int w = tid >> 5, lane = tid & 31;
    int lr = lane >> 2, lc = lane & 3;
    int arow0 = w * 16 + lr;

    float d[4][4];
#pragma unroll
    for (int nc = 0; nc < 4; nc++)
        d[nc][0] = d[nc][1] = d[nc][2] = d[nc][3] = 0.f;

#pragma unroll
    for (int kc = 0; kc < 8; kc++) {
        float af[4];
        af[0] = pt[arow0 * 68 + kc * 8 + lc];
        af[1] = pt[(arow0 + 8) * 68 + kc * 8 + lc];
        af[2] = pt[arow0 * 68 + kc * 8 + lc + 4];
        af[3] = pt[(arow0 + 8) * 68 + kc * 8 + lc + 4];
        unsigned ah[4], al[4];
#pragma unroll
        for (int t = 0; t < 4; t++) {
            CVT_TF32(ah[t], af[t]);
            float res = af[t] - __uint_as_float(ah[t]);
            CVT_TF32(al[t], res);
        }
#pragma unroll
        for (int nc = 0; nc < 4; nc++) {
            float bf0 = wbs[(kc * 8 + lc) * WS + nc * 8 + lr];
            float bf1 = wbs[(kc * 8 + lc + 4) * WS + nc * 8 + lr];
            unsigned bh0, bh1, bl0, bl1;
            CVT_TF32(bh0, bf0);
            CVT_TF32(bh1, bf1);
            float r0 = bf0 - __uint_as_float(bh0);
            float r1 = bf1 - __uint_as_float(bh1);
            CVT_TF32(bl0, r0);
            CVT_TF32(bl1, r1);
            mma_tf32(d[nc][0], d[nc][1], d[nc][2], d[nc][3],
                     ah[0], ah[1], ah[2], ah[3], bh0, bh1);
            mma_tf32(d[nc][0], d[nc][1], d[nc][2], d[nc][3],
                     ah[0], ah[1], ah[2], ah[3], bl0, bl1);
            mma_tf32(d[nc][0], d[nc][1], d[nc][2], d[nc][3],
                     al[0], al[1], al[2], al[3], bh0, bh1);
        }
    }

    float mu0 = mus[arow0],     rs0 = rstds[arow0];
    float mu1 = mus[arow0 + 8], rs1 = rstds[arow0 + 8];
    size_t row = rowbase + arow0;
#pragma unroll
    for (int nc = 0; nc < 4; nc++) {
        int col = nc * 8 + 2 * lc;
        float s0 = ssm[col], s1 = ssm[col + 1];
        float c0 = c1sm[col], c1v = c1sm[col + 1];
        float2 o0, o1;
        o0.x = rs0 * (d[nc][0] - mu0 * s0) + c0;
        o0.y = rs0 * (d[nc][1] - mu0 * s1) + c1v;
        o1.x = rs1 * (d[nc][2] - mu1 * s0) + c0;
        o1.y = rs1 * (d[nc][3] - mu1 * s1) + c1v;
        *(float2*)&g_bias[row * NH + col]       = o0;
        *(float2*)&g_bias[(row + 8) * NH + col] = o1;
    }
}

// ---------------------------------------------------------------------------
// Kernel F: streaming attention + force (EXACT R8/R14-proven version).
// 256 threads = 8 warps; lane = head h, warp w covers j == w (mod 8).
// ---------------------------------------------------------------------------
__global__ void __launch_bounds__(256, 2) attn_kernel(
    const float* __restrict__ delta, float* __restrict__ out) {
    int c = blockIdx.y;
    int ibase = blockIdx.x * 4;
    int tid = threadIdx.x;
    int w = tid >> 5, h = tid & 31;

    ulonglong2 q[4][4];
#pragma unroll
    for (int ii = 0; ii < 4; ii++) {
        const float* qp = g_q + ((size_t)(c * NN) + ibase + ii) * ED + h * HD;
#pragma unroll
        for (int t = 0; t < 4; t++)
            q[ii][t] = *(const ulonglong2*)(qp + t * 4);
    }

    float l[4]  = {0.f, 0.f, 0.f, 0.f};
    float n0[4] = {0.f, 0.f, 0.f, 0.f};
    float n1[4] = {0.f, 0.f, 0.f, 0.f};
    float n2[4] = {0.f, 0.f, 0.f, 0.f};

    const size_t cb = (size_t)(c * NN) + ibase;
#pragma unroll 2
    for (int j = w; j < NN; j += 8) {
        const float* kp = g_k + ((size_t)(c * NN) + j) * ED + h * HD;
        ulonglong2 k0 = *(const ulonglong2*)(kp + 0);
        ulonglong2 k1 = *(const ulonglong2*)(kp + 4);
        ulonglong2 k2 = *(const ulonglong2*)(kp + 8);
        ulonglong2 k3 = *(const ulonglong2*)(kp + 12);
        float vfv = g_vf[((size_t)(c * NN) + j) * NH + h];
        const float* dp = delta + (cb * NN + j) * 3;
        const float* bp = g_bias + (cb * NN + j) * NH + h;
#pragma unroll
        for (int ii = 0; ii < 4; ii++) {
            unsigned long long a;
            MUL2(a, q[ii][0].x, k0.x);
            FMA2(a, q[ii][0].y, k0.y);
            FMA2(a, q[ii][1].x, k1.x);
            FMA2(a, q[ii][1].y, k1.y);
            FMA2(a, q[ii][2].x, k2.x);
            FMA2(a, q[ii][2].y, k2.y);
            FMA2(a, q[ii][3].x, k3.x);
            FMA2(a, q[ii][3].y, k3.y);
            float lo, hi; UNPACK2(lo, hi, a);
            float z = lo + hi + bp[(size_t)ii * (NN * NH)];
            float we = __expf(z);
            float wv = we * vfv;
            float d0 = dp[ii * (NN * 3) + 0];
            float d1 = dp[ii * (NN * 3) + 1];
            float d2 = dp[ii * (NN * 3) + 2];
            l[ii]  += we;
            n0[ii] += wv * d0;
            n1[ii] += wv * d1;
            n2[ii] += wv * d2;
        }
    }

    __shared__ float ms[8][4][32][4];
#pragma unroll
    for (int ii = 0; ii < 4; ii++)
        *(float4*)&ms[w][ii][h][0] = make_float4(l[ii], n0[ii], n1[ii], n2[ii]);
    __syncthreads();

    if (w < 4) {
        int ii = w;
        float L = 0.f, F0 = 0.f, F1 = 0.f, F2 = 0.f;
#pragma unroll
        for (int ww = 0; ww < 8; ww++) {
            float4 a = *(const float4*)&ms[ww][ii][h][0];
            L += a.x; F0 += a.y; F1 += a.z; F2 += a.w;
        }
        // per-(i, head) normalization BEFORE summing over heads
        float inv = 1.f / L;
        F0 *= inv; F1 *= inv; F2 *= inv;
#pragma unroll
        for (int off = 16; off; off >>= 1) {
            F0 += __shfl_down_sync(0xffffffffu, F0, off);
            F1 += __shfl_down_sync(0xffffffffu, F1, off);
            F2 += __shfl_down_sync(0xffffffffu, F2, off);
        }
        if (h == 0) {
            float* op = out + ((size_t)(c * NN) + ibase + ii) * 3;
            op[0] = F0; op[1] = F1; op[2] = F2;
        }
    }
}

// ---------------------------------------------------------------------------
// Host launch
// ---------------------------------------------------------------------------
extern "C" void kernel_launch(void* const* d_in, const int* in_sizes, int n_in,
                              void* d_out, int out_size) {
    const float* query = (const float*)d_in[0];
    const float* pair  = (const float*)d_in[1];
    const float* delta = (const float*)d_in[2];
    const float* lnqg  = (const float*)d_in[3];
    const float* lnqb  = (const float*)d_in[4];
    const float* lnpg  = (const float*)d_in[5];
    const float* lnpb  = (const float*)d_in[6];
    const float* Wq    = (const float*)d_in[7];
    const float* Wk    = (const float*)d_in[8];
    const float* Wv    = (const float*)d_in[9];
    const float* Wb    = (const float*)d_in[10];
    const float* bb    = (const float*)d_in[11];
    const float* Wf    = (const float*)d_in[12];
    float* out = (float*)d_out;

    ln_q_kernel<<<NC * NN, 128>>>(query, lnqg, lnqb);

    dim3 gg(ED / 64, (NC * NN) / 128, 3);
    qkv_gemm_tc<<<gg, 256>>>(Wq, Wk, Wv, Wf);

    bias_kernel<<<(NC * NN * NN) / BM, 256>>>(pair, lnpg, lnpb, Wb, bb);

    attn_kernel<<<dim3(NN / 4, NC), 256>>>(delta, out);
}

// round 17
// speedup vs baseline: 1.5012x; 1.0090x over previous
#include <cuda_runtime.h>
#include <cuda_bf16.h>

// Problem constants
#define NC 4
#define NN 512
#define ED 512
#define PD 64
#define NH 32
#define HD 16

// wbs row stride: 40 -> B-fragment bank conflict-free (bias kernel)
#define WS 40

// f32x2 packed-math helpers (sm_100+)
#define FMA2(acc, a, b) asm("fma.rn.f32x2 %0, %1, %2, %0;" : "+l"(acc) : "l"(a), "l"(b))
#define MUL2(d, a, b)   asm("mul.rn.f32x2 %0, %1, %2;" : "=l"(d) : "l"(a), "l"(b))
#define PACK2(d, x)     asm("mov.b64 %0, {%1, %1};" : "=l"(d) : "f"(x))
#define UNPACK2(lo, hi, v) asm("mov.b64 {%0, %1}, %2;" : "=f"(lo), "=f"(hi) : "l"(v))

#define CVT_TF32(u, f) asm("cvt.rna.tf32.f32 %0, %1;" : "=r"(u) : "f"(f))

__device__ __forceinline__ void mma_tf32(float& d0, float& d1, float& d2, float& d3,
                                         unsigned a0, unsigned a1, unsigned a2, unsigned a3,
                                         unsigned b0, unsigned b1) {
    asm volatile("mma.sync.aligned.m16n8k8.row.col.f32.tf32.tf32.f32 "
                 "{%0,%1,%2,%3}, {%4,%5,%6,%7}, {%8,%9}, {%0,%1,%2,%3};"
                 : "+f"(d0), "+f"(d1), "+f"(d2), "+f"(d3)
                 : "r"(a0), "r"(a1), "r"(a2), "r"(a3), "r"(b0), "r"(b1));
}

// Scratch (static device arrays; no allocations allowed)
__device__ float g_xq[NC * NN * ED];
__device__ float g_q [NC * NN * ED];
__device__ float g_k [NC * NN * ED];
__device__ float g_v [NC * NN * ED];
__device__ float g_vf[NC * NN * NH];                 // [c, j, h]
__device__ float g_bias[(size_t)NC * NN * NN * NH];  // [c, i, j, h]

// ---------------------------------------------------------------------------
// Kernel A: LayerNorm(query) -> g_xq.
// ---------------------------------------------------------------------------
__global__ void ln_q_kernel(const float* __restrict__ x,
                            const float* __restrict__ g,
                            const float* __restrict__ b) {
    int row = blockIdx.x;
    const float* xr = x + (size_t)row * ED;
    float* o = g_xq + (size_t)row * ED;
    int tid = threadIdx.x;  // 128
    float v[4];
    float s = 0.f, s2 = 0.f;
#pragma unroll
    for (int t = 0; t < 4; t++) {
        float vv = xr[tid + t * 128];
        v[t] = vv; s += vv; s2 += vv * vv;
    }
#pragma unroll
    for (int off = 16; off; off >>= 1) {
        s  += __shfl_down_sync(0xffffffffu, s,  off);
        s2 += __shfl_down_sync(0xffffffffu, s2, off);
    }
    __shared__ float sh[8];
    if ((tid & 31) == 0) { sh[tid >> 5] = s; sh[4 + (tid >> 5)] = s2; }
    __syncthreads();
    float S  = sh[0] + sh[1] + sh[2] + sh[3];
    float S2 = sh[4] + sh[5] + sh[6] + sh[7];
    float mu   = S * (1.f / ED);
    float var  = S2 * (1.f / ED) - mu * mu;
    float rstd = rsqrtf(var + 1e-5f);
#pragma unroll
    for (int t = 0; t < 4; t++) {
        int e = tid + t * 128;
        o[e] = (v[t] - mu) * rstd * g[e] + b[e];
    }
}

// ---------------------------------------------------------------------------
// Kernel B: QKV projection GEMM on tensor cores (R14-proven, 3-mma tf32).
// V case (blockIdx.z==2) computes vf in the epilogue (R16-proven).
// ---------------------------------------------------------------------------
#define QBK 16
__global__ void __launch_bounds__(256) qkv_gemm_tc(
    const float* __restrict__ Wq, const float* __restrict__ Wk,
    const float* __restrict__ Wv, const float* __restrict__ Wf) {
    const float* W; float* O; float scale = 1.f;
    if (blockIdx.z == 0)      { W = Wq; O = g_q; scale = 0.25f; }
    else if (blockIdx.z == 1) { W = Wk; O = g_k; }
    else                      { W = Wv; O = g_v; }
    const float* A = g_xq;

    __shared__ float Ahi[128 * 20], Alo[128 * 20];
    __shared__ float Bhi[64 * 20],  Blo[64 * 20];
    __shared__ float vft[128][4];

    int tid = threadIdx.x;
    int m0 = blockIdx.y * 128, n0 = blockIdx.x * 64;
    int w = tid >> 5, lane = tid & 31;
    int lr = lane >> 2, lc = lane & 3;
    int arow0 = w * 16 + lr;

    if (blockIdx.z == 2) {
        for (int idx = tid; idx < 128 * 4; idx += 256)
            ((float*)vft)[idx] = 0.f;
    }

    float d[8][4];
#pragma unroll
    for (int nc = 0; nc < 8; nc++)
        d[nc][0] = d[nc][1] = d[nc][2] = d[nc][3] = 0.f;

    for (int k0 = 0; k0 < ED; k0 += QBK) {
        __syncthreads();
#pragma unroll
        for (int t = 0; t < 2; t++) {
            int idx = tid + t * 256;
            int row = idx >> 2, f4 = idx & 3;
            float4 v = *(const float4*)&A[(size_t)(m0 + row) * ED + k0 + f4 * 4];
            float4 hi4, lo4;
            unsigned u;
            CVT_TF32(u, v.x); hi4.x = __uint_as_float(u); { float r = v.x - hi4.x; CVT_TF32(u, r); lo4.x = __uint_as_float(u); }
            CVT_TF32(u, v.y); hi4.y = __uint_as_float(u); { float r = v.y - hi4.y; CVT_TF32(u, r); lo4.y = __uint_as_float(u); }
            CVT_TF32(u, v.z); hi4.z = __uint_as_float(u); { float r = v.z - hi4.z; CVT_TF32(u, r); lo4.z = __uint_as_float(u); }
            CVT_TF32(u, v.w); hi4.w = __uint_as_float(u); { float r = v.w - hi4.w; CVT_TF32(u, r); lo4.w = __uint_as_float(u); }
            *(float4*)&Ahi[row * 20 + f4 * 4] = hi4;
            *(float4*)&Alo[row * 20 + f4 * 4] = lo4;
        }
        {
            int row = tid >> 2, f4 = tid & 3;
            float4 v = *(const float4*)&W[(size_t)(n0 + row) * ED + k0 + f4 * 4];
            float4 hi4, lo4;
            unsigned u;
            CVT_TF32(u, v.x); hi4.x = __uint_as_float(u); { float r = v.x - hi4.x; CVT_TF32(u, r); lo4.x = __uint_as_float(u); }
            CVT_TF32(u, v.y); hi4.y = __uint_as_float(u); { float r = v.y - hi4.y; CVT_TF32(u, r); lo4.y = __uint_as_float(u); }
            CVT_TF32(u, v.z); hi4.z = __uint_as_float(u); { float r = v.z - hi4.z; CVT_TF32(u, r); lo4.z = __uint_as_float(u); }
            CVT_TF32(u, v.w); hi4.w = __uint_as_float(u); { float r = v.w - hi4.w; CVT_TF32(u, r); lo4.w = __uint_as_float(u); }
            *(float4*)&Bhi[row * 20 + f4 * 4] = hi4;
            *(float4*)&Blo[row * 20 + f4 * 4] = lo4;
        }
        __syncthreads();

#pragma unroll
        for (int kc = 0; kc < QBK / 8; kc++) {
            unsigned ah[4], al[4];
            ah[0] = __float_as_uint(Ahi[arow0 * 20 + kc * 8 + lc]);
            ah[1] = __float_as_uint(Ahi[(arow0 + 8) * 20 + kc * 8 + lc]);
            ah[2] = __float_as_uint(Ahi[arow0 * 20 + kc * 8 + lc + 4]);
            ah[3] = __float_as_uint(Ahi[(arow0 + 8) * 20 + kc * 8 + lc + 4]);
            al[0] = __float_as_uint(Alo[arow0 * 20 + kc * 8 + lc]);
            al[1] = __float_as_uint(Alo[(arow0 + 8) * 20 + kc * 8 + lc]);
            al[2] = __float_as_uint(Alo[arow0 * 20 + kc * 8 + lc + 4]);
            al[3] = __float_as_uint(Alo[(arow0 + 8) * 20 + kc * 8 + lc + 4]);
#pragma unroll
            for (int nc = 0; nc < 8; nc++) {
                int nrow = nc * 8 + lr;
                unsigned bh0 = __float_as_uint(Bhi[nrow * 20 + kc * 8 + lc]);
                unsigned bh1 = __float_as_uint(Bhi[nrow * 20 + kc * 8 + lc + 4]);
                unsigned bl0 = __float_as_uint(Blo[nrow * 20 + kc * 8 + lc]);
                unsigned bl1 = __float_as_uint(Blo[nrow * 20 + kc * 8 + lc + 4]);
                mma_tf32(d[nc][0], d[nc][1], d[nc][2], d[nc][3],
                         ah[0], ah[1], ah[2], ah[3], bh0, bh1);
                mma_tf32(d[nc][0], d[nc][1], d[nc][2], d[nc][3],
                         ah[0], ah[1], ah[2], ah[3], bl0, bl1);
                mma_tf32(d[nc][0], d[nc][1], d[nc][2], d[nc][3],
                         al[0], al[1], al[2], al[3], bh0, bh1);
            }
        }
    }

    size_t row = (size_t)(m0 + arow0);
#pragma unroll
    for (int nc = 0; nc < 8; nc++) {
        int col = n0 + nc * 8 + 2 * lc;
        *(float2*)&O[row * ED + col] =
            make_float2(d[nc][0] * scale, d[nc][1] * scale);
        *(float2*)&O[(row + 8) * ED + col] =
            make_float2(d[nc][2] * scale, d[nc][3] * scale);
    }

    if (blockIdx.z == 2) {
        __syncthreads();
#pragma unroll
        for (int nc = 0; nc < 8; nc++) {
            int cl = nc * 8 + 2 * lc;
            int hl = nc >> 1;
            float w0 = Wf[n0 + cl];
            float w1 = Wf[n0 + cl + 1];
            atomicAdd(&vft[arow0][hl],     d[nc][0] * w0 + d[nc][1] * w1);
            atomicAdd(&vft[arow0 + 8][hl], d[nc][2] * w0 + d[nc][3] * w1);
        }
        __syncthreads();
        int h0 = n0 >> 4;
        for (int idx = tid; idx < 128 * 4; idx += 256) {
            int r = idx >> 2, hl = idx & 3;
            g_vf[(size_t)(m0 + r) * NH + h0 + hl] = vft[r][hl];
        }
    }
}

// ---------------------------------------------------------------------------
// Kernel E: bias GEMM on tensor cores, LN folded into epilogue (R12 exact).
// ---------------------------------------------------------------------------
#define BM 128
__global__ void __launch_bounds__(256) bias_kernel(
    const float* __restrict__ pair, const float* __restrict__ lnpg,
    const float* __restrict__ lnpb, const float* __restrict__ Wb,
    const float* __restrict__ bb) {
    __shared__ float pt[BM * 68];
    __shared__ float wbs[64 * WS];
    __shared__ float mus[BM], rstds[BM];
    __shared__ float ssm[NH], c1sm[NH];
    int tid = threadIdx.x;
    size_t rowbase = (size_t)blockIdx.x * BM;

    const float4* src = (const float4*)(pair + rowbase * PD);
#pragma unroll
    for (int t = 0; t < 8; t++) {
        int idx = tid + t * 256;
        int row = idx >> 4, f4 = idx & 15;
        float4 v = src[idx];
        *(float4*)&pt[row * 68 + f4 * 4] = v;
    }
    for (int idx = tid; idx < 2048; idx += 256) {
        int n = idx >> 6, k = idx & 63;
        wbs[k * WS + n] = lnpg[k] * Wb[idx];
    }
    __syncthreads();

    {
        int row = tid >> 1, half = tid & 1;
        const float* pr = pt + row * 68 + half * 32;
        float s = 0.f, s2 = 0.f;
#pragma unroll
        for (int t = 0; t < 8; t++) {
            float4 v = *(const float4*)&pr[t * 4];
            s  += v.x + v.y + v.z + v.w;
            s2 += v.x * v.x + v.y * v.y + v.z * v.z + v.w * v.w;
        }
        s  += __shfl_xor_sync(0xffffffffu, s, 1);
        s2 += __shfl_xor_sync(0xffffffffu, s2, 1);
        if (half == 0) {
            float mu  = s * (1.f / PD);
            float var = s2 * (1.f / PD) - mu * mu;
            mus[row]   = mu;
            rstds[row] = rsqrtf(var + 1e-5f);
        }
    }
    {
        int h = tid >> 3, kq = tid & 7;
        float sv = 0.f, c1 = 0.f;
#pragma unroll
        for (int t = 0; t < 8; t++) {
            int k = kq * 8 + t;
            sv += wbs[k * WS + h];
            c1 += lnpb[k] * Wb[h * PD + k];
        }
#pragma unroll
        for (int off = 1; off < 8; off <<= 1) {
            sv += __shfl_xor_sync(0xffffffffu, sv, off, 8);
            c1 += __shfl_xor_sync(0xffffffffu, c1, off, 8);
        }
        if (kq == 0) { ssm[h] = sv; c1sm[h] = c1 + bb[h]; }
    }
    __syncthreads();

    int w = tid >> 5, lane = tid & 31;
    int lr = lane >> 2, lc = lane & 3;
    int arow0 = w * 16 + lr;

    float d[4][4];
#pragma unroll
    for (int nc = 0; nc < 4; nc++)
        d[nc][0] = d[nc][1] = d[nc][2] = d[nc][3] = 0.f;

#pragma unroll
    for (int kc = 0; kc < 8; kc++) {
        float af[4];
        af[0] = pt[arow0 * 68 + kc * 8 + lc];
        af[1] = pt[(arow0 + 8) * 68 + kc * 8 + lc];
        af[2] = pt[arow0 * 68 + kc * 8 + lc + 4];
        af[3] = pt[(arow0 + 8) * 68 + kc * 8 + lc + 4];
        unsigned ah[4], al[4];
#pragma unroll
        for (int t = 0; t < 4; t++) {
            CVT_TF32(ah[t], af[t]);
            float res = af[t] - __uint_as_float(ah[t]);
            CVT_TF32(al[t], res);
        }
#pragma unroll
        for (int nc = 0; nc < 4; nc++) {
            float bf0 = wbs[(kc * 8 + lc) * WS + nc * 8 + lr];
            float bf1 = wbs[(kc * 8 + lc + 4) * WS + nc * 8 + lr];
            unsigned bh0, bh1, bl0, bl1;
            CVT_TF32(bh0, bf0);
            CVT_TF32(bh1, bf1);
            float r0 = bf0 - __uint_as_float(bh0);
            float r1 = bf1 - __uint_as_float(bh1);
            CVT_TF32(bl0, r0);
            CVT_TF32(bl1, r1);
            mma_tf32(d[nc][0], d[nc][1], d[nc][2], d[nc][3],
                     ah[0], ah[1], ah[2], ah[3], bh0, bh1);
            mma_tf32(d[nc][0], d[nc][1], d[nc][2], d[nc][3],
                     ah[0], ah[1], ah[2], ah[3], bl0, bl1);
            mma_tf32(d[nc][0], d[nc][1], d[nc][2], d[nc][3],
                     al[0], al[1], al[2], al[3], bh0, bh1);
        }
    }

    float mu0 = mus[arow0],     rs0 = rstds[arow0];
    float mu1 = mus[arow0 + 8], rs1 = rstds[arow0 + 8];
    size_t row = rowbase + arow0;
#pragma unroll
    for (int nc = 0; nc < 4; nc++) {
        int col = nc * 8 + 2 * lc;
        float s0 = ssm[col], s1 = ssm[col + 1];
        float c0 = c1sm[col], c1v = c1sm[col + 1];
        float2 o0, o1;
        o0.x = rs0 * (d[nc][0] - mu0 * s0) + c0;
        o0.y = rs0 * (d[nc][1] - mu0 * s1) + c1v;
        o1.x = rs1 * (d[nc][2] - mu1 * s0) + c0;
        o1.y = rs1 * (d[nc][3] - mu1 * s1) + c1v;
        *(float2*)&g_bias[row * NH + col]       = o0;
        *(float2*)&g_bias[(row + 8) * NH + col] = o1;
    }
}

// ---------------------------------------------------------------------------
// Kernel F: streaming attention + force (R8/R14-proven version).
// ---------------------------------------------------------------------------
__global__ void __launch_bounds__(256, 2) attn_kernel(
    const float* __restrict__ delta, float* __restrict__ out) {
    int c = blockIdx.y;
    int ibase = blockIdx.x * 4;
    int tid = threadIdx.x;
    int w = tid >> 5, h = tid & 31;

    ulonglong2 q[4][4];
#pragma unroll
    for (int ii = 0; ii < 4; ii++) {
        const float* qp = g_q + ((size_t)(c * NN) + ibase + ii) * ED + h * HD;
#pragma unroll
        for (int t = 0; t < 4; t++)
            q[ii][t] = *(const ulonglong2*)(qp + t * 4);
    }

    float l[4]  = {0.f, 0.f, 0.f, 0.f};
    float n0[4] = {0.f, 0.f, 0.f, 0.f};
    float n1[4] = {0.f, 0.f, 0.f, 0.f};
    float n2[4] = {0.f, 0.f, 0.f, 0.f};

    const size_t cb = (size_t)(c * NN) + ibase;
#pragma unroll 2
    for (int j = w; j < NN; j += 8) {
        const float* kp = g_k + ((size_t)(c * NN) + j) * ED + h * HD;
        ulonglong2 k0 = *(const ulonglong2*)(kp + 0);
        ulonglong2 k1 = *(const ulonglong2*)(kp + 4);
        ulonglong2 k2 = *(const ulonglong2*)(kp + 8);
        ulonglong2 k3 = *(const ulonglong2*)(kp + 12);
        float vfv = g_vf[((size_t)(c * NN) + j) * NH + h];
        const float* dp = delta + (cb * NN + j) * 3;
        const float* bp = g_bias + (cb * NN + j) * NH + h;
#pragma unroll
        for (int ii = 0; ii < 4; ii++) {
            unsigned long long a;
            MUL2(a, q[ii][0].x, k0.x);
            FMA2(a, q[ii][0].y, k0.y);
            FMA2(a, q[ii][1].x, k1.x);
            FMA2(a, q[ii][1].y, k1.y);
            FMA2(a, q[ii][2].x, k2.x);
            FMA2(a, q[ii][2].y, k2.y);
            FMA2(a, q[ii][3].x, k3.x);
            FMA2(a, q[ii][3].y, k3.y);
            float lo, hi; UNPACK2(lo, hi, a);
            float z = lo + hi + bp[(size_t)ii * (NN * NH)];
            float we = __expf(z);
            float wv = we * vfv;
            float d0 = dp[ii * (NN * 3) + 0];
            float d1 = dp[ii * (NN * 3) + 1];
            float d2 = dp[ii * (NN * 3) + 2];
            l[ii]  += we;
            n0[ii] += wv * d0;
            n1[ii] += wv * d1;
            n2[ii] += wv * d2;
        }
    }

    __shared__ float ms[8][4][32][4];
#pragma unroll
    for (int ii = 0; ii < 4; ii++)
        *(float4*)&ms[w][ii][h][0] = make_float4(l[ii], n0[ii], n1[ii], n2[ii]);
    __syncthreads();

    if (w < 4) {
        int ii = w;
        float L = 0.f, F0 = 0.f, F1 = 0.f, F2 = 0.f;
#pragma unroll
        for (int ww = 0; ww < 8; ww++) {
            float4 a = *(const float4*)&ms[ww][ii][h][0];
            L += a.x; F0 += a.y; F1 += a.z; F2 += a.w;
        }
        // per-(i, head) normalization BEFORE summing over heads
        float inv = 1.f / L;
        F0 *= inv; F1 *= inv; F2 *= inv;
#pragma unroll
        for (int off = 16; off; off >>= 1) {
            F0 += __shfl_down_sync(0xffffffffu, F0, off);
            F1 += __shfl_down_sync(0xffffffffu, F1, off);
            F2 += __shfl_down_sync(0xffffffffu, F2, off);
        }
        if (h == 0) {
            float* op = out + ((size_t)(c * NN) + ibase + ii) * 3;
            op[0] = F0; op[1] = F1; op[2] = F2;
        }
    }
}

// ---------------------------------------------------------------------------
// Host launch: overlap bias (stream s2) with ln+qkv (main stream) via the
// standard capture-safe fork-join event pattern; join before attn.
// ---------------------------------------------------------------------------
extern "C" void kernel_launch(void* const* d_in, const int* in_sizes, int n_in,
                              void* d_out, int out_size) {
    const float* query = (const float*)d_in[0];
    const float* pair  = (const float*)d_in[1];
    const float* delta = (const float*)d_in[2];
    const float* lnqg  = (const float*)d_in[3];
    const float* lnqb  = (const float*)d_in[4];
    const float* lnpg  = (const float*)d_in[5];
    const float* lnpb  = (const float*)d_in[6];
    const float* Wq    = (const float*)d_in[7];
    const float* Wk    = (const float*)d_in[8];
    const float* Wv    = (const float*)d_in[9];
    const float* Wb    = (const float*)d_in[10];
    const float* bb    = (const float*)d_in[11];
    const float* Wf    = (const float*)d_in[12];
    float* out = (float*)d_out;

    static cudaStream_t s2 = nullptr;
    static cudaEvent_t e_fork = nullptr, e_join = nullptr;
    if (!s2) {
        cudaStreamCreateWithFlags(&s2, cudaStreamNonBlocking);
        cudaEventCreateWithFlags(&e_fork, cudaEventDisableTiming);
        cudaEventCreateWithFlags(&e_join, cudaEventDisableTiming);
    }

    // fork: bias chain on s2, ln+qkv chain on the launch (default) stream
    cudaEventRecord(e_fork, 0);
    cudaStreamWaitEvent(s2, e_fork, 0);

    bias_kernel<<<(NC * NN * NN) / BM, 256, 0, s2>>>(pair, lnpg, lnpb, Wb, bb);

    ln_q_kernel<<<NC * NN, 128>>>(query, lnqg, lnqb);
    dim3 gg(ED / 64, (NC * NN) / 128, 3);
    qkv_gemm_tc<<<gg, 256>>>(Wq, Wk, Wv, Wf);

    // join: attn needs both chains
    cudaEventRecord(e_join, s2);
    cudaStreamWaitEvent(0, e_join, 0);

    attn_kernel<<<dim3(NN / 4, NC), 256>>>(delta, out);
}